// round 10
// baseline (speedup 1.0000x reference)
#include <cuda_runtime.h>
#include <math.h>

// ---------------------------------------------------------------------------
// AttentionOnDetail: B=8, T=8192, C=128, H=8, T0=16, Np=512, sel=4, S=65
// R9: single change vs R3/R8 baseline (61.5/61.9us): out GEMM rebuilt as
// 512-block (32 ksplit x 2 coltile x 8 b) stage-1 + 32-way reduce.
// score/qkvg/attn byte-identical to R3.
// ---------------------------------------------------------------------------

#define EPS_F 1.1920929e-07f
#define INV_SQRT_C 0.08838834764831845f  // 1/sqrt(128)

static const int B = 8;
static const int T = 8192;
static const int H = 8;
static const int NP = 512;
static const int ROWS = 64;
static const int QKVG = 4096;
static const int OKSPL = 32;   // out GEMM K-splits (K=1024 -> chunks of 32)

// scratch (device globals; no allocation allowed)
__device__ float g_score[B * NP];
__device__ float g_G[(size_t)B * ROWS * QKVG];        // gathered qkvg, 8 MB
__device__ float g_Z[(size_t)B * 64 * 1024];          // gated attention out
__device__ float g_P[(size_t)OKSPL * 512 * 128];      // out GEMM partials, 8 MB

// ---- packed fp32x2 helpers ------------------------------------------------
__device__ __forceinline__ unsigned long long fma2(unsigned long long a,
                                                   unsigned long long b,
                                                   unsigned long long c) {
    unsigned long long d;
    asm("fma.rn.f32x2 %0, %1, %2, %3;" : "=l"(d) : "l"(a), "l"(b), "l"(c));
    return d;
}
__device__ __forceinline__ unsigned long long pk2(float a, float b) {
    unsigned long long d;
    asm("mov.b64 %0, {%1, %2};" : "=l"(d) : "f"(a), "f"(b));
    return d;
}
__device__ __forceinline__ void up2(unsigned long long v, float& a, float& b) {
    asm("mov.b64 {%0, %1}, %2;" : "=f"(a), "=f"(b) : "l"(v));
}

// ---------------------------------------------------------------------------
// K1: per-patch score logit: dot(x_patch, patch_w) * rsqrt(mean(x^2)+eps)
// grid = B*NP blocks (4096), 256 threads. Reads all of x (33.5 MB). HBM-bound.
// ---------------------------------------------------------------------------
__global__ void score_kernel(const float* __restrict__ x,
                             const float* __restrict__ pw) {
    int bp = blockIdx.x;
    const float4* xp = (const float4*)(x + (size_t)bp * 2048);
    const float4* pw4 = (const float4*)pw;
    int tid = threadIdx.x;
    float sq = 0.f, dt = 0.f;
    #pragma unroll
    for (int i = tid; i < 512; i += 256) {
        float4 v = xp[i];
        float4 w = pw4[i];
        sq += v.x * v.x + v.y * v.y + v.z * v.z + v.w * v.w;
        dt += v.x * w.x + v.y * w.y + v.z * w.z + v.w * w.w;
    }
    for (int o = 16; o; o >>= 1) {
        sq += __shfl_xor_sync(0xffffffffu, sq, o);
        dt += __shfl_xor_sync(0xffffffffu, dt, o);
    }
    __shared__ float s_sq[8], s_dt[8];
    int w = tid >> 5, ln = tid & 31;
    if (ln == 0) { s_sq[w] = sq; s_dt[w] = dt; }
    __syncthreads();
    if (tid == 0) {
        float tsq = 0.f, tdt = 0.f;
        #pragma unroll
        for (int i = 0; i < 8; i++) { tsq += s_sq[i]; tdt += s_dt[i]; }
        g_score[bp] = tdt * rsqrtf(tsq * (1.0f / 2048.0f) + EPS_F);
    }
}

// ---------------------------------------------------------------------------
// K2: topk (warp-scan, fused) + gathered qkvg GEMM with fp32x2 FMA.
// grid = (32 col-tiles of 128, B), 256 threads. K-chunk 32 (8 syncs total).
// Dynamic smem: xsT (transposed, stride 66) + ws[32][128].   [R3 verbatim]
// ---------------------------------------------------------------------------
#define QK_SMEM ((128 * 66 + 32 * 128) * 4)

__global__ __launch_bounds__(256) void qkvg_kernel(const float* __restrict__ x,
                                                   const float* __restrict__ W) {
    extern __shared__ __align__(16) float qsm[];
    float* xsT = qsm;               // 128 * 66
    float* ws = qsm + 128 * 66;     // 32 * 128
    __shared__ int tk[4];

    int b = blockIdx.y;
    int o0 = blockIdx.x * 128;
    int tid = threadIdx.x;

    // ---- warp 0: top-4 of 512 scores, sorted ascending ----
    if (tid < 32) {
        float v[16];
        #pragma unroll
        for (int i = 0; i < 16; i++) v[i] = g_score[b * 512 + tid + 32 * i];
        int picks[4];
        #pragma unroll
        for (int r = 0; r < 4; r++) {
            float m = v[0]; int mi = 0;
            #pragma unroll
            for (int i = 1; i < 16; i++)
                if (v[i] > m) { m = v[i]; mi = i; }
            int gi = tid + 32 * mi;
            #pragma unroll
            for (int o = 16; o; o >>= 1) {
                float m2 = __shfl_xor_sync(0xffffffffu, m, o);
                int g2 = __shfl_xor_sync(0xffffffffu, gi, o);
                if (m2 > m || (m2 == m && g2 < gi)) { m = m2; gi = g2; }
            }
            picks[r] = gi;
            if ((gi & 31) == tid) v[gi >> 5] = -INFINITY;
        }
        #pragma unroll
        for (int i = 0; i < 4; i++)
            #pragma unroll
            for (int j = i + 1; j < 4; j++)
                if (picks[j] < picks[i]) { int t = picks[i]; picks[i] = picks[j]; picks[j] = t; }
        if (tid == 0) {
            tk[0] = picks[0]; tk[1] = picks[1]; tk[2] = picks[2]; tk[3] = picks[3];
        }
    }
    __syncthreads();

    // ---- gather x rows transposed into xsT[k][row] ----
    for (int i = tid; i < 2048; i += 256) {
        int r = i >> 5;
        int c4 = i & 31;
        int token = tk[r >> 4] * 16 + (r & 15);
        float4 v = *(const float4*)(x + ((size_t)b * T + token) * 128 + 4 * c4);
        xsT[(4 * c4 + 0) * 66 + r] = v.x;
        xsT[(4 * c4 + 1) * 66 + r] = v.y;
        xsT[(4 * c4 + 2) * 66 + r] = v.z;
        xsT[(4 * c4 + 3) * 66 + r] = v.w;
    }

    unsigned long long acc[4][4];
    #pragma unroll
    for (int i = 0; i < 4; i++)
        #pragma unroll
        for (int c = 0; c < 4; c++) acc[i][c] = 0ull;

    int tx = tid & 31, ty = tid >> 5;
    int c0 = 4 * tx, r0 = 8 * ty;

    for (int kc = 0; kc < 4; kc++) {
        __syncthreads();
        // ws[kk][o] = W[(o0+o)*128 + kc*32 + kk], 1024 float4 loads
        for (int i = tid; i < 1024; i += 256) {
            int o = i >> 3, kq = i & 7;
            float4 wv = *(const float4*)(W + (size_t)(o0 + o) * 128 + kc * 32 + 4 * kq);
            ws[(4 * kq + 0) * 128 + o] = wv.x;
            ws[(4 * kq + 1) * 128 + o] = wv.y;
            ws[(4 * kq + 2) * 128 + o] = wv.z;
            ws[(4 * kq + 3) * 128 + o] = wv.w;
        }
        __syncthreads();
        #pragma unroll 8
        for (int kk = 0; kk < 32; kk++) {
            int k = kc * 32 + kk;
            const float* xrow = xsT + k * 66 + r0;
            unsigned long long x0 = *(const unsigned long long*)(xrow + 0);
            unsigned long long x1 = *(const unsigned long long*)(xrow + 2);
            unsigned long long x2 = *(const unsigned long long*)(xrow + 4);
            unsigned long long x3 = *(const unsigned long long*)(xrow + 6);
            float4 wv = *(const float4*)(ws + kk * 128 + c0);
            unsigned long long w0 = pk2(wv.x, wv.x);
            unsigned long long w1 = pk2(wv.y, wv.y);
            unsigned long long w2 = pk2(wv.z, wv.z);
            unsigned long long w3 = pk2(wv.w, wv.w);
            acc[0][0] = fma2(x0, w0, acc[0][0]);
            acc[0][1] = fma2(x0, w1, acc[0][1]);
            acc[0][2] = fma2(x0, w2, acc[0][2]);
            acc[0][3] = fma2(x0, w3, acc[0][3]);
            acc[1][0] = fma2(x1, w0, acc[1][0]);
            acc[1][1] = fma2(x1, w1, acc[1][1]);
            acc[1][2] = fma2(x1, w2, acc[1][2]);
            acc[1][3] = fma2(x1, w3, acc[1][3]);
            acc[2][0] = fma2(x2, w0, acc[2][0]);
            acc[2][1] = fma2(x2, w1, acc[2][1]);
            acc[2][2] = fma2(x2, w2, acc[2][2]);
            acc[2][3] = fma2(x2, w3, acc[2][3]);
            acc[3][0] = fma2(x3, w0, acc[3][0]);
            acc[3][1] = fma2(x3, w1, acc[3][1]);
            acc[3][2] = fma2(x3, w2, acc[3][2]);
            acc[3][3] = fma2(x3, w3, acc[3][3]);
        }
    }

    #pragma unroll
    for (int i = 0; i < 4; i++) {
        float lo0, hi0, lo1, hi1, lo2, hi2, lo3, hi3;
        up2(acc[i][0], lo0, hi0);
        up2(acc[i][1], lo1, hi1);
        up2(acc[i][2], lo2, hi2);
        up2(acc[i][3], lo3, hi3);
        size_t base = ((size_t)b * ROWS + r0 + 2 * i) * QKVG + o0 + c0;
        *(float4*)&g_G[base] = make_float4(lo0, lo1, lo2, lo3);
        *(float4*)&g_G[base + QKVG] = make_float4(hi0, hi1, hi2, hi3);
    }
}

// ---------------------------------------------------------------------------
// K3: attention with fused rope+rmsnorm, per (b,h,query-chunk of 32).
// grid = (2, H, B) = 128 blocks, 256 threads (8 warps).   [R3 verbatim]
// ---------------------------------------------------------------------------
#define KS_STR 132
#define VS_STR 130
#define QS_OFF (65 * KS_STR + 65 * VS_STR + 2)
#define PB_OFF (QS_OFF + 8 * 128)
#define ATTN_SMEM_FLOATS (PB_OFF + 8 * 66)

__global__ __launch_bounds__(256) void attn_kernel(
    const float* __restrict__ sink, const float* __restrict__ cosb,
    const float* __restrict__ sinb, const float* __restrict__ tao) {
    extern __shared__ __align__(16) float sm[];
    float* ks = sm;
    float* vs = sm + 65 * KS_STR;
    float* qs = sm + QS_OFF;
    float* pb = sm + PB_OFF;

    int chunk = blockIdx.x, h = blockIdx.y, b = blockIdx.z;
    int tid = threadIdx.x, w = tid >> 5, lane = tid & 31;
    float tao0 = tao[0], tao1 = tao[1];

    int maxT = 32 + 32 * chunk;

    for (int t = w; t <= maxT; t += 8) {
        float a0, a1, a2, a3, v0, v1, v2, v3;
        if (t == 0) {
            const float* sp = sink + h * 128;
            a0 = sp[lane]; a1 = sp[lane + 32]; a2 = sp[lane + 64]; a3 = sp[lane + 96];
            v0 = a0; v1 = a1; v2 = a2; v3 = a3;
        } else {
            int sg = t - 1, i4 = sg >> 4, m = sg & 15;
            size_t base = ((size_t)b * ROWS + i4 * 16 + (m >> 2)) * QKVG +
                          (m & 3) * 1024 + h * 128;
            const float* Kr = g_G + base + 4 * (size_t)QKVG;
            const float* Vr = g_G + base + 8 * (size_t)QKVG;
            a0 = Kr[lane]; a1 = Kr[lane + 32]; a2 = Kr[lane + 64]; a3 = Kr[lane + 96];
            v0 = Vr[lane]; v1 = Vr[lane + 32]; v2 = Vr[lane + 64]; v3 = Vr[lane + 96];
        }
        float cs0 = cosb[t * 64 + lane], sn0 = sinb[t * 64 + lane];
        float cs1 = cosb[t * 64 + lane + 32], sn1 = sinb[t * 64 + lane + 32];
        float r0 = a0 * cs0 + a2 * sn0;
        float r2 = a2 * cs0 - a0 * sn0;
        float r1 = a1 * cs1 + a3 * sn1;
        float r3 = a3 * cs1 - a1 * sn1;
        float ss = r0 * r0 + r1 * r1 + r2 * r2 + r3 * r3;
        #pragma unroll
        for (int o = 16; o; o >>= 1) ss += __shfl_xor_sync(0xffffffffu, ss, o);
        float rn = rsqrtf(ss * (1.0f / 128.0f) + EPS_F) * tao1;
        ks[t * KS_STR + lane] = r0 * rn;
        ks[t * KS_STR + lane + 32] = r1 * rn;
        ks[t * KS_STR + lane + 64] = r2 * rn;
        ks[t * KS_STR + lane + 96] = r3 * rn;
        vs[t * VS_STR + lane] = v0;
        vs[t * VS_STR + lane + 32] = v1;
        vs[t * VS_STR + lane + 64] = v2;
        vs[t * VS_STR + lane + 96] = v3;
    }
    __syncthreads();

    float* qr = qs + w * 128;
    int c2 = 2 * lane;

    for (int jj = 0; jj < 4; jj++) {
        int s = chunk * 32 + 1 + w + 8 * jj;
        int sg = s - 1, i4 = sg >> 4, m = sg & 15;
        size_t gbase = ((size_t)b * ROWS + i4 * 16 + (m >> 2)) * QKVG +
                       (m & 3) * 1024 + h * 128;
        {
            const float* Qr = g_G + gbase;
            float a0 = Qr[lane], a1 = Qr[lane + 32], a2 = Qr[lane + 64], a3 = Qr[lane + 96];
            float cs0 = cosb[s * 64 + lane], sn0 = sinb[s * 64 + lane];
            float cs1 = cosb[s * 64 + lane + 32], sn1 = sinb[s * 64 + lane + 32];
            float r0 = a0 * cs0 + a2 * sn0;
            float r2 = a2 * cs0 - a0 * sn0;
            float r1 = a1 * cs1 + a3 * sn1;
            float r3 = a3 * cs1 - a1 * sn1;
            float ss = r0 * r0 + r1 * r1 + r2 * r2 + r3 * r3;
            #pragma unroll
            for (int o = 16; o; o >>= 1) ss += __shfl_xor_sync(0xffffffffu, ss, o);
            float rn = rsqrtf(ss * (1.0f / 128.0f) + EPS_F) * tao0;
            qr[lane] = r0 * rn;
            qr[lane + 32] = r1 * rn;
            qr[lane + 64] = r2 * rn;
            qr[lane + 96] = r3 * rn;
        }
        __syncwarp();

        float l[3];
        int nt = 0;
        float lmax = -INFINITY;
        for (int t = lane; t <= s; t += 32) {
            const float* kr = ks + t * KS_STR;
            unsigned long long A0 = 0ull, A1 = 0ull;
            #pragma unroll
            for (int c = 0; c < 128; c += 4) {
                ulonglong2 qv = *reinterpret_cast<const ulonglong2*>(qr + c);
                ulonglong2 kv = *reinterpret_cast<const ulonglong2*>(kr + c);
                A0 = fma2(qv.x, kv.x, A0);
                A1 = fma2(qv.y, kv.y, A1);
            }
            float x0, x1, x2, x3;
            up2(A0, x0, x1);
            up2(A1, x2, x3);
            float acc = ((x0 + x1) + (x2 + x3)) * INV_SQRT_C;
            l[nt++] = acc;
            lmax = fmaxf(lmax, acc);
        }
        #pragma unroll
        for (int o = 16; o; o >>= 1)
            lmax = fmaxf(lmax, __shfl_xor_sync(0xffffffffu, lmax, o));
        float se = 0.f;
        #pragma unroll
        for (int q = 0; q < 3; q++)
            if (q < nt) { l[q] = expf(l[q] - lmax); se += l[q]; }
        #pragma unroll
        for (int o = 16; o; o >>= 1)
            se += __shfl_xor_sync(0xffffffffu, se, o);
        float inv = 1.0f / se;
        {
            int q = 0;
            for (int t = lane; t <= s; t += 32) pb[w * 66 + t] = l[q++] * inv;
        }
        __syncwarp();

        unsigned long long Y0 = 0ull, Y1 = 0ull;
        for (int t = 0; t <= s; t++) {
            float p = pb[w * 66 + t];
            unsigned long long pp = pk2(p, p);
            Y0 = fma2(*reinterpret_cast<const unsigned long long*>(vs + t * VS_STR + c2), pp, Y0);
            Y1 = fma2(*reinterpret_cast<const unsigned long long*>(vs + t * VS_STR + 64 + c2), pp, Y1);
        }

        const float* Gr = g_G + gbase + 12 * (size_t)QKVG;
        float2 ga = *(const float2*)(Gr + c2);
        float2 gb2 = *(const float2*)(Gr + 64 + c2);
        float y0, y1, y2, y3;
        up2(Y0, y0, y1);
        up2(Y1, y2, y3);
        float* Zb = g_Z + ((size_t)b * 64 + sg) * 1024 + h * 128;
        *(float2*)(Zb + c2) = make_float2(y0 * (1.0f / (1.0f + expf(-ga.x))),
                                          y1 * (1.0f / (1.0f + expf(-ga.y))));
        *(float2*)(Zb + 64 + c2) = make_float2(y2 * (1.0f / (1.0f + expf(-gb2.x))),
                                               y3 * (1.0f / (1.0f + expf(-gb2.y))));
        __syncwarp();
    }
}

// ---------------------------------------------------------------------------
// K4a: out GEMM stage 1 — 512 blocks: (32 ksplits of 32, 2 coltiles of 64, B).
// 256 threads; tile 64 rows x 64 cols, K=32. ~17.5 KB smem, 4 LDG/thread,
// single sync. Per-thread 4 rows (2 f32x2 pairs) x 4 cols.
// ---------------------------------------------------------------------------
#define O1_SMEM ((32 * 68 + 32 * 64) * 4)

__global__ __launch_bounds__(256) void out1_kernel(const float* __restrict__ Wout) {
    extern __shared__ __align__(16) float osm[];
    float* zsT = osm;               // 32 k x 68 (64 rows + pad)
    float* ws = osm + 32 * 68;      // 32 k x 64 o

    int ksp = blockIdx.x;
    int O0 = blockIdx.y * 64;
    int b = blockIdx.z;
    int k0 = ksp * 32;
    int tid = threadIdx.x;

    // zsT[k][r] = Z[b, r, k0+k]  (512 float4 loads, 2/thread)
    for (int i = tid; i < 512; i += 256) {
        int r = i >> 3, kq = i & 7;
        float4 v = *(const float4*)(g_Z + ((size_t)b * 64 + r) * 1024 + k0 + 4 * kq);
        zsT[(4 * kq + 0) * 68 + r] = v.x;
        zsT[(4 * kq + 1) * 68 + r] = v.y;
        zsT[(4 * kq + 2) * 68 + r] = v.z;
        zsT[(4 * kq + 3) * 68 + r] = v.w;
    }
    // ws[k][o] = Wout[(O0+o)*1024 + k0 + k]  (512 float4 loads, 2/thread)
    for (int i = tid; i < 512; i += 256) {
        int o = i >> 3, kq = i & 7;
        float4 v = *(const float4*)(Wout + (size_t)(O0 + o) * 1024 + k0 + 4 * kq);
        ws[(4 * kq + 0) * 64 + o] = v.x;
        ws[(4 * kq + 1) * 64 + o] = v.y;
        ws[(4 * kq + 2) * 64 + o] = v.z;
        ws[(4 * kq + 3) * 64 + o] = v.w;
    }
    __syncthreads();

    unsigned long long acc[2][4];
    #pragma unroll
    for (int i = 0; i < 2; i++)
        #pragma unroll
        for (int c = 0; c < 4; c++) acc[i][c] = 0ull;

    int tx16 = tid & 15, ty16 = tid >> 4;
    int c0 = 4 * tx16, r0 = 4 * ty16;

    #pragma unroll
    for (int k = 0; k < 32; k++) {
        const float* zr = zsT + k * 68 + r0;
        unsigned long long x0 = *(const unsigned long long*)(zr + 0);
        unsigned long long x1 = *(const unsigned long long*)(zr + 2);
        float4 wv = *(const float4*)(ws + k * 64 + c0);
        unsigned long long w0 = pk2(wv.x, wv.x);
        unsigned long long w1 = pk2(wv.y, wv.y);
        unsigned long long w2 = pk2(wv.z, wv.z);
        unsigned long long w3 = pk2(wv.w, wv.w);
        acc[0][0] = fma2(x0, w0, acc[0][0]);
        acc[0][1] = fma2(x0, w1, acc[0][1]);
        acc[0][2] = fma2(x0, w2, acc[0][2]);
        acc[0][3] = fma2(x0, w3, acc[0][3]);
        acc[1][0] = fma2(x1, w0, acc[1][0]);
        acc[1][1] = fma2(x1, w1, acc[1][1]);
        acc[1][2] = fma2(x1, w2, acc[1][2]);
        acc[1][3] = fma2(x1, w3, acc[1][3]);
    }

    // partials: g_P[(ksp*512 + b*64 + row)*128 + O0 + col]
    #pragma unroll
    for (int i = 0; i < 2; i++) {
        float lo0, hi0, lo1, hi1, lo2, hi2, lo3, hi3;
        up2(acc[i][0], lo0, hi0);
        up2(acc[i][1], lo1, hi1);
        up2(acc[i][2], lo2, hi2);
        up2(acc[i][3], lo3, hi3);
        size_t base = ((size_t)(ksp * 512 + b * 64 + r0 + 2 * i)) * 128 + O0 + c0;
        *(float4*)&g_P[base] = make_float4(lo0, lo1, lo2, lo3);
        *(float4*)&g_P[base + 128] = make_float4(hi0, hi1, hi2, hi3);
    }
}

// ---------------------------------------------------------------------------
// K4b: reduce 32 split-K partials. grid = 128 blocks x 128 threads,
// one float4 output per thread; partials come from L2.
// ---------------------------------------------------------------------------
__global__ __launch_bounds__(128) void out2_kernel(float* __restrict__ out) {
    int g = blockIdx.x * 128 + threadIdx.x;   // 0..16383 float4 slots
    float4 a = make_float4(0.f, 0.f, 0.f, 0.f);
    #pragma unroll
    for (int ks = 0; ks < OKSPL; ks++) {
        float4 v = *(const float4*)(g_P + (size_t)ks * 65536 + 4 * (size_t)g);
        a.x += v.x; a.y += v.y; a.z += v.z; a.w += v.w;
    }
    *(float4*)(out + 4 * (size_t)g) = a;
}

// ---------------------------------------------------------------------------
// launch
// ---------------------------------------------------------------------------
extern "C" void kernel_launch(void* const* d_in, const int* in_sizes, int n_in,
                              void* d_out, int out_size) {
    const float *x = nullptr, *cosb = nullptr, *sinb = nullptr, *sink = nullptr,
                *Wqkvg = nullptr, *pw = nullptr, *Wout = nullptr, *tao = nullptr;
    for (int i = 0; i < n_in; i++) {
        const float* p = (const float*)d_in[i];
        switch (in_sizes[i]) {
            case 8 * 8192 * 128: x = p; break;
            case 65 * 64: if (!cosb) cosb = p; else sinb = p; break;
            case 8 * 128: sink = p; break;
            case 4096 * 128: Wqkvg = p; break;
            case 2048: pw = p; break;
            case 128 * 1024: Wout = p; break;
            case 2: tao = p; break;
            default: break;
        }
    }
    float* out = (float*)d_out;

    cudaFuncSetAttribute(attn_kernel, cudaFuncAttributeMaxDynamicSharedMemorySize,
                         ATTN_SMEM_FLOATS * (int)sizeof(float));
    cudaFuncSetAttribute(qkvg_kernel, cudaFuncAttributeMaxDynamicSharedMemorySize,
                         QK_SMEM);
    cudaFuncSetAttribute(out1_kernel, cudaFuncAttributeMaxDynamicSharedMemorySize,
                         O1_SMEM);

    score_kernel<<<B * NP, 256>>>(x, pw);
    qkvg_kernel<<<dim3(32, B), 256, QK_SMEM>>>(x, Wqkvg);
    attn_kernel<<<dim3(2, H, B), 256, ATTN_SMEM_FLOATS * (int)sizeof(float)>>>(
        sink, cosb, sinb, tao);
    out1_kernel<<<dim3(OKSPL, 2, B), 256, O1_SMEM>>>(Wout);
    out2_kernel<<<128, 128>>>(out);
    (void)out_size;
}

// round 11
// speedup vs baseline: 1.0721x; 1.0721x over previous
#include <cuda_runtime.h>
#include <math.h>

// ---------------------------------------------------------------------------
// AttentionOnDetail: B=8, T=8192, C=128, H=8, T0=16, Np=512, sel=4, S=65
// R10: single change vs R3/R8 baseline (61.5/61.9us): attn_kernel widened to
// 512 threads (16 warps) — K/V build stride 16, 2 query rounds per warp.
// score/qkvg/out1/out2 byte-identical to R3.
// ---------------------------------------------------------------------------

#define EPS_F 1.1920929e-07f
#define INV_SQRT_C 0.08838834764831845f  // 1/sqrt(128)

static const int B = 8;
static const int T = 8192;
static const int H = 8;
static const int NP = 512;
static const int ROWS = 64;
static const int QKVG = 4096;
static const int OKSPL = 16;   // out GEMM K-splits (K=1024 -> chunks of 64)

// scratch (device globals; no allocation allowed)
__device__ float g_score[B * NP];
__device__ float g_G[(size_t)B * ROWS * QKVG];        // gathered qkvg, 8 MB
__device__ float g_Z[(size_t)B * 64 * 1024];          // gated attention out
__device__ float g_P[(size_t)OKSPL * 512 * 128];      // out GEMM partials, 4 MB

// ---- packed fp32x2 helpers ------------------------------------------------
__device__ __forceinline__ unsigned long long fma2(unsigned long long a,
                                                   unsigned long long b,
                                                   unsigned long long c) {
    unsigned long long d;
    asm("fma.rn.f32x2 %0, %1, %2, %3;" : "=l"(d) : "l"(a), "l"(b), "l"(c));
    return d;
}
__device__ __forceinline__ unsigned long long pk2(float a, float b) {
    unsigned long long d;
    asm("mov.b64 %0, {%1, %2};" : "=l"(d) : "f"(a), "f"(b));
    return d;
}
__device__ __forceinline__ void up2(unsigned long long v, float& a, float& b) {
    asm("mov.b64 {%0, %1}, %2;" : "=f"(a), "=f"(b) : "l"(v));
}

// ---------------------------------------------------------------------------
// K1: per-patch score logit: dot(x_patch, patch_w) * rsqrt(mean(x^2)+eps)
// grid = B*NP blocks (4096), 256 threads. Reads all of x (33.5 MB). HBM-bound.
// ---------------------------------------------------------------------------
__global__ void score_kernel(const float* __restrict__ x,
                             const float* __restrict__ pw) {
    int bp = blockIdx.x;
    const float4* xp = (const float4*)(x + (size_t)bp * 2048);
    const float4* pw4 = (const float4*)pw;
    int tid = threadIdx.x;
    float sq = 0.f, dt = 0.f;
    #pragma unroll
    for (int i = tid; i < 512; i += 256) {
        float4 v = xp[i];
        float4 w = pw4[i];
        sq += v.x * v.x + v.y * v.y + v.z * v.z + v.w * v.w;
        dt += v.x * w.x + v.y * w.y + v.z * w.z + v.w * w.w;
    }
    for (int o = 16; o; o >>= 1) {
        sq += __shfl_xor_sync(0xffffffffu, sq, o);
        dt += __shfl_xor_sync(0xffffffffu, dt, o);
    }
    __shared__ float s_sq[8], s_dt[8];
    int w = tid >> 5, ln = tid & 31;
    if (ln == 0) { s_sq[w] = sq; s_dt[w] = dt; }
    __syncthreads();
    if (tid == 0) {
        float tsq = 0.f, tdt = 0.f;
        #pragma unroll
        for (int i = 0; i < 8; i++) { tsq += s_sq[i]; tdt += s_dt[i]; }
        g_score[bp] = tdt * rsqrtf(tsq * (1.0f / 2048.0f) + EPS_F);
    }
}

// ---------------------------------------------------------------------------
// K2: topk (warp-scan, fused) + gathered qkvg GEMM with fp32x2 FMA.
// grid = (32 col-tiles of 128, B), 256 threads. K-chunk 32 (8 syncs total).
// Dynamic smem: xsT (transposed, stride 66) + ws[32][128].   [R3 verbatim]
// ---------------------------------------------------------------------------
#define QK_SMEM ((128 * 66 + 32 * 128) * 4)

__global__ __launch_bounds__(256) void qkvg_kernel(const float* __restrict__ x,
                                                   const float* __restrict__ W) {
    extern __shared__ __align__(16) float qsm[];
    float* xsT = qsm;               // 128 * 66
    float* ws = qsm + 128 * 66;     // 32 * 128
    __shared__ int tk[4];

    int b = blockIdx.y;
    int o0 = blockIdx.x * 128;
    int tid = threadIdx.x;

    // ---- warp 0: top-4 of 512 scores, sorted ascending ----
    if (tid < 32) {
        float v[16];
        #pragma unroll
        for (int i = 0; i < 16; i++) v[i] = g_score[b * 512 + tid + 32 * i];
        int picks[4];
        #pragma unroll
        for (int r = 0; r < 4; r++) {
            float m = v[0]; int mi = 0;
            #pragma unroll
            for (int i = 1; i < 16; i++)
                if (v[i] > m) { m = v[i]; mi = i; }
            int gi = tid + 32 * mi;
            #pragma unroll
            for (int o = 16; o; o >>= 1) {
                float m2 = __shfl_xor_sync(0xffffffffu, m, o);
                int g2 = __shfl_xor_sync(0xffffffffu, gi, o);
                if (m2 > m || (m2 == m && g2 < gi)) { m = m2; gi = g2; }
            }
            picks[r] = gi;
            if ((gi & 31) == tid) v[gi >> 5] = -INFINITY;
        }
        #pragma unroll
        for (int i = 0; i < 4; i++)
            #pragma unroll
            for (int j = i + 1; j < 4; j++)
                if (picks[j] < picks[i]) { int t = picks[i]; picks[i] = picks[j]; picks[j] = t; }
        if (tid == 0) {
            tk[0] = picks[0]; tk[1] = picks[1]; tk[2] = picks[2]; tk[3] = picks[3];
        }
    }
    __syncthreads();

    // ---- gather x rows transposed into xsT[k][row] ----
    for (int i = tid; i < 2048; i += 256) {
        int r = i >> 5;
        int c4 = i & 31;
        int token = tk[r >> 4] * 16 + (r & 15);
        float4 v = *(const float4*)(x + ((size_t)b * T + token) * 128 + 4 * c4);
        xsT[(4 * c4 + 0) * 66 + r] = v.x;
        xsT[(4 * c4 + 1) * 66 + r] = v.y;
        xsT[(4 * c4 + 2) * 66 + r] = v.z;
        xsT[(4 * c4 + 3) * 66 + r] = v.w;
    }

    unsigned long long acc[4][4];
    #pragma unroll
    for (int i = 0; i < 4; i++)
        #pragma unroll
        for (int c = 0; c < 4; c++) acc[i][c] = 0ull;

    int tx = tid & 31, ty = tid >> 5;
    int c0 = 4 * tx, r0 = 8 * ty;

    for (int kc = 0; kc < 4; kc++) {
        __syncthreads();
        // ws[kk][o] = W[(o0+o)*128 + kc*32 + kk], 1024 float4 loads
        for (int i = tid; i < 1024; i += 256) {
            int o = i >> 3, kq = i & 7;
            float4 wv = *(const float4*)(W + (size_t)(o0 + o) * 128 + kc * 32 + 4 * kq);
            ws[(4 * kq + 0) * 128 + o] = wv.x;
            ws[(4 * kq + 1) * 128 + o] = wv.y;
            ws[(4 * kq + 2) * 128 + o] = wv.z;
            ws[(4 * kq + 3) * 128 + o] = wv.w;
        }
        __syncthreads();
        #pragma unroll 8
        for (int kk = 0; kk < 32; kk++) {
            int k = kc * 32 + kk;
            const float* xrow = xsT + k * 66 + r0;
            unsigned long long x0 = *(const unsigned long long*)(xrow + 0);
            unsigned long long x1 = *(const unsigned long long*)(xrow + 2);
            unsigned long long x2 = *(const unsigned long long*)(xrow + 4);
            unsigned long long x3 = *(const unsigned long long*)(xrow + 6);
            float4 wv = *(const float4*)(ws + kk * 128 + c0);
            unsigned long long w0 = pk2(wv.x, wv.x);
            unsigned long long w1 = pk2(wv.y, wv.y);
            unsigned long long w2 = pk2(wv.z, wv.z);
            unsigned long long w3 = pk2(wv.w, wv.w);
            acc[0][0] = fma2(x0, w0, acc[0][0]);
            acc[0][1] = fma2(x0, w1, acc[0][1]);
            acc[0][2] = fma2(x0, w2, acc[0][2]);
            acc[0][3] = fma2(x0, w3, acc[0][3]);
            acc[1][0] = fma2(x1, w0, acc[1][0]);
            acc[1][1] = fma2(x1, w1, acc[1][1]);
            acc[1][2] = fma2(x1, w2, acc[1][2]);
            acc[1][3] = fma2(x1, w3, acc[1][3]);
            acc[2][0] = fma2(x2, w0, acc[2][0]);
            acc[2][1] = fma2(x2, w1, acc[2][1]);
            acc[2][2] = fma2(x2, w2, acc[2][2]);
            acc[2][3] = fma2(x2, w3, acc[2][3]);
            acc[3][0] = fma2(x3, w0, acc[3][0]);
            acc[3][1] = fma2(x3, w1, acc[3][1]);
            acc[3][2] = fma2(x3, w2, acc[3][2]);
            acc[3][3] = fma2(x3, w3, acc[3][3]);
        }
    }

    #pragma unroll
    for (int i = 0; i < 4; i++) {
        float lo0, hi0, lo1, hi1, lo2, hi2, lo3, hi3;
        up2(acc[i][0], lo0, hi0);
        up2(acc[i][1], lo1, hi1);
        up2(acc[i][2], lo2, hi2);
        up2(acc[i][3], lo3, hi3);
        size_t base = ((size_t)b * ROWS + r0 + 2 * i) * QKVG + o0 + c0;
        *(float4*)&g_G[base] = make_float4(lo0, lo1, lo2, lo3);
        *(float4*)&g_G[base + QKVG] = make_float4(hi0, hi1, hi2, hi3);
    }
}

// ---------------------------------------------------------------------------
// K3: attention with fused rope+rmsnorm, per (b,h,query-chunk of 32).
// grid = (2, H, B) = 128 blocks, 512 threads (16 warps): K/V build stride 16,
// 2 query rounds per warp (was 8 warps / 4 rounds).
// ---------------------------------------------------------------------------
#define KS_STR 132
#define VS_STR 130
#define QS_OFF (65 * KS_STR + 65 * VS_STR + 2)
#define PB_OFF (QS_OFF + 16 * 128)
#define ATTN_SMEM_FLOATS (PB_OFF + 16 * 66)

__global__ __launch_bounds__(512) void attn_kernel(
    const float* __restrict__ sink, const float* __restrict__ cosb,
    const float* __restrict__ sinb, const float* __restrict__ tao) {
    extern __shared__ __align__(16) float sm[];
    float* ks = sm;
    float* vs = sm + 65 * KS_STR;
    float* qs = sm + QS_OFF;
    float* pb = sm + PB_OFF;

    int chunk = blockIdx.x, h = blockIdx.y, b = blockIdx.z;
    int tid = threadIdx.x, w = tid >> 5, lane = tid & 31;
    float tao0 = tao[0], tao1 = tao[1];

    int maxT = 32 + 32 * chunk;

    for (int t = w; t <= maxT; t += 16) {
        float a0, a1, a2, a3, v0, v1, v2, v3;
        if (t == 0) {
            const float* sp = sink + h * 128;
            a0 = sp[lane]; a1 = sp[lane + 32]; a2 = sp[lane + 64]; a3 = sp[lane + 96];
            v0 = a0; v1 = a1; v2 = a2; v3 = a3;
        } else {
            int sg = t - 1, i4 = sg >> 4, m = sg & 15;
            size_t base = ((size_t)b * ROWS + i4 * 16 + (m >> 2)) * QKVG +
                          (m & 3) * 1024 + h * 128;
            const float* Kr = g_G + base + 4 * (size_t)QKVG;
            const float* Vr = g_G + base + 8 * (size_t)QKVG;
            a0 = Kr[lane]; a1 = Kr[lane + 32]; a2 = Kr[lane + 64]; a3 = Kr[lane + 96];
            v0 = Vr[lane]; v1 = Vr[lane + 32]; v2 = Vr[lane + 64]; v3 = Vr[lane + 96];
        }
        float cs0 = cosb[t * 64 + lane], sn0 = sinb[t * 64 + lane];
        float cs1 = cosb[t * 64 + lane + 32], sn1 = sinb[t * 64 + lane + 32];
        float r0 = a0 * cs0 + a2 * sn0;
        float r2 = a2 * cs0 - a0 * sn0;
        float r1 = a1 * cs1 + a3 * sn1;
        float r3 = a3 * cs1 - a1 * sn1;
        float ss = r0 * r0 + r1 * r1 + r2 * r2 + r3 * r3;
        #pragma unroll
        for (int o = 16; o; o >>= 1) ss += __shfl_xor_sync(0xffffffffu, ss, o);
        float rn = rsqrtf(ss * (1.0f / 128.0f) + EPS_F) * tao1;
        ks[t * KS_STR + lane] = r0 * rn;
        ks[t * KS_STR + lane + 32] = r1 * rn;
        ks[t * KS_STR + lane + 64] = r2 * rn;
        ks[t * KS_STR + lane + 96] = r3 * rn;
        vs[t * VS_STR + lane] = v0;
        vs[t * VS_STR + lane + 32] = v1;
        vs[t * VS_STR + lane + 64] = v2;
        vs[t * VS_STR + lane + 96] = v3;
    }
    __syncthreads();

    float* qr = qs + w * 128;
    int c2 = 2 * lane;

    for (int jj = 0; jj < 2; jj++) {
        int s = chunk * 32 + 1 + w + 16 * jj;
        int sg = s - 1, i4 = sg >> 4, m = sg & 15;
        size_t gbase = ((size_t)b * ROWS + i4 * 16 + (m >> 2)) * QKVG +
                       (m & 3) * 1024 + h * 128;
        {
            const float* Qr = g_G + gbase;
            float a0 = Qr[lane], a1 = Qr[lane + 32], a2 = Qr[lane + 64], a3 = Qr[lane + 96];
            float cs0 = cosb[s * 64 + lane], sn0 = sinb[s * 64 + lane];
            float cs1 = cosb[s * 64 + lane + 32], sn1 = sinb[s * 64 + lane + 32];
            float r0 = a0 * cs0 + a2 * sn0;
            float r2 = a2 * cs0 - a0 * sn0;
            float r1 = a1 * cs1 + a3 * sn1;
            float r3 = a3 * cs1 - a1 * sn1;
            float ss = r0 * r0 + r1 * r1 + r2 * r2 + r3 * r3;
            #pragma unroll
            for (int o = 16; o; o >>= 1) ss += __shfl_xor_sync(0xffffffffu, ss, o);
            float rn = rsqrtf(ss * (1.0f / 128.0f) + EPS_F) * tao0;
            qr[lane] = r0 * rn;
            qr[lane + 32] = r1 * rn;
            qr[lane + 64] = r2 * rn;
            qr[lane + 96] = r3 * rn;
        }
        __syncwarp();

        float l[3];
        int nt = 0;
        float lmax = -INFINITY;
        for (int t = lane; t <= s; t += 32) {
            const float* kr = ks + t * KS_STR;
            unsigned long long A0 = 0ull, A1 = 0ull;
            #pragma unroll
            for (int c = 0; c < 128; c += 4) {
                ulonglong2 qv = *reinterpret_cast<const ulonglong2*>(qr + c);
                ulonglong2 kv = *reinterpret_cast<const ulonglong2*>(kr + c);
                A0 = fma2(qv.x, kv.x, A0);
                A1 = fma2(qv.y, kv.y, A1);
            }
            float x0, x1, x2, x3;
            up2(A0, x0, x1);
            up2(A1, x2, x3);
            float acc = ((x0 + x1) + (x2 + x3)) * INV_SQRT_C;
            l[nt++] = acc;
            lmax = fmaxf(lmax, acc);
        }
        #pragma unroll
        for (int o = 16; o; o >>= 1)
            lmax = fmaxf(lmax, __shfl_xor_sync(0xffffffffu, lmax, o));
        float se = 0.f;
        #pragma unroll
        for (int q = 0; q < 3; q++)
            if (q < nt) { l[q] = expf(l[q] - lmax); se += l[q]; }
        #pragma unroll
        for (int o = 16; o; o >>= 1)
            se += __shfl_xor_sync(0xffffffffu, se, o);
        float inv = 1.0f / se;
        {
            int q = 0;
            for (int t = lane; t <= s; t += 32) pb[w * 66 + t] = l[q++] * inv;
        }
        __syncwarp();

        unsigned long long Y0 = 0ull, Y1 = 0ull;
        for (int t = 0; t <= s; t++) {
            float p = pb[w * 66 + t];
            unsigned long long pp = pk2(p, p);
            Y0 = fma2(*reinterpret_cast<const unsigned long long*>(vs + t * VS_STR + c2), pp, Y0);
            Y1 = fma2(*reinterpret_cast<const unsigned long long*>(vs + t * VS_STR + 64 + c2), pp, Y1);
        }

        const float* Gr = g_G + gbase + 12 * (size_t)QKVG;
        float2 ga = *(const float2*)(Gr + c2);
        float2 gb2 = *(const float2*)(Gr + 64 + c2);
        float y0, y1, y2, y3;
        up2(Y0, y0, y1);
        up2(Y1, y2, y3);
        float* Zb = g_Z + ((size_t)b * 64 + sg) * 1024 + h * 128;
        *(float2*)(Zb + c2) = make_float2(y0 * (1.0f / (1.0f + expf(-ga.x))),
                                          y1 * (1.0f / (1.0f + expf(-ga.y))));
        *(float2*)(Zb + 64 + c2) = make_float2(y2 * (1.0f / (1.0f + expf(-gb2.x))),
                                               y3 * (1.0f / (1.0f + expf(-gb2.y))));
        __syncwarp();
    }
}

// ---------------------------------------------------------------------------
// K4a: out GEMM stage 1 (split-K partials, no atomics).   [R3 verbatim]
// grid = (16 ksplits of 64, B) = 128 blocks, 256 threads (8 warps).
// ---------------------------------------------------------------------------
#define O1_SMEM ((64 * 68 + 64 * 128) * 4)

__global__ __launch_bounds__(256) void out1_kernel(const float* __restrict__ Wout) {
    extern __shared__ __align__(16) float osm[];
    float* zsT = osm;              // 64 k x 68 (rows 64 + pad)
    float* ws = osm + 64 * 68;     // 64 k x 128 o

    int ksp = blockIdx.x, b = blockIdx.y;
    int k0 = ksp * 64;
    int tid = threadIdx.x;

    for (int i = tid; i < 1024; i += 256) {
        int r = i >> 4, kq = i & 15;
        float4 v = *(const float4*)(g_Z + ((size_t)b * 64 + r) * 1024 + k0 + 4 * kq);
        zsT[(4 * kq + 0) * 68 + r] = v.x;
        zsT[(4 * kq + 1) * 68 + r] = v.y;
        zsT[(4 * kq + 2) * 68 + r] = v.z;
        zsT[(4 * kq + 3) * 68 + r] = v.w;
    }
    for (int i = tid; i < 2048; i += 256) {
        int o = i >> 4, kq = i & 15;
        float4 v = *(const float4*)(Wout + (size_t)o * 1024 + k0 + 4 * kq);
        ws[(4 * kq + 0) * 128 + o] = v.x;
        ws[(4 * kq + 1) * 128 + o] = v.y;
        ws[(4 * kq + 2) * 128 + o] = v.z;
        ws[(4 * kq + 3) * 128 + o] = v.w;
    }
    __syncthreads();

    unsigned long long acc[4][4];
    #pragma unroll
    for (int i = 0; i < 4; i++)
        #pragma unroll
        for (int c = 0; c < 4; c++) acc[i][c] = 0ull;

    int tx = tid & 31, ty = tid >> 5;
    int c0 = 4 * tx, r0 = 8 * ty;

    #pragma unroll 8
    for (int k = 0; k < 64; k++) {
        const float* zr = zsT + k * 68 + r0;
        unsigned long long x0 = *(const unsigned long long*)(zr + 0);
        unsigned long long x1 = *(const unsigned long long*)(zr + 2);
        unsigned long long x2 = *(const unsigned long long*)(zr + 4);
        unsigned long long x3 = *(const unsigned long long*)(zr + 6);
        float4 wv = *(const float4*)(ws + k * 128 + c0);
        unsigned long long w0 = pk2(wv.x, wv.x);
        unsigned long long w1 = pk2(wv.y, wv.y);
        unsigned long long w2 = pk2(wv.z, wv.z);
        unsigned long long w3 = pk2(wv.w, wv.w);
        acc[0][0] = fma2(x0, w0, acc[0][0]);
        acc[0][1] = fma2(x0, w1, acc[0][1]);
        acc[0][2] = fma2(x0, w2, acc[0][2]);
        acc[0][3] = fma2(x0, w3, acc[0][3]);
        acc[1][0] = fma2(x1, w0, acc[1][0]);
        acc[1][1] = fma2(x1, w1, acc[1][1]);
        acc[1][2] = fma2(x1, w2, acc[1][2]);
        acc[1][3] = fma2(x1, w3, acc[1][3]);
        acc[2][0] = fma2(x2, w0, acc[2][0]);
        acc[2][1] = fma2(x2, w1, acc[2][1]);
        acc[2][2] = fma2(x2, w2, acc[2][2]);
        acc[2][3] = fma2(x2, w3, acc[2][3]);
        acc[3][0] = fma2(x3, w0, acc[3][0]);
        acc[3][1] = fma2(x3, w1, acc[3][1]);
        acc[3][2] = fma2(x3, w2, acc[3][2]);
        acc[3][3] = fma2(x3, w3, acc[3][3]);
    }

    #pragma unroll
    for (int i = 0; i < 4; i++) {
        float lo0, hi0, lo1, hi1, lo2, hi2, lo3, hi3;
        up2(acc[i][0], lo0, hi0);
        up2(acc[i][1], lo1, hi1);
        up2(acc[i][2], lo2, hi2);
        up2(acc[i][3], lo3, hi3);
        size_t base = ((size_t)(ksp * 512 + b * 64 + r0 + 2 * i)) * 128 + c0;
        *(float4*)&g_P[base] = make_float4(lo0, lo1, lo2, lo3);
        *(float4*)&g_P[base + 128] = make_float4(hi0, hi1, hi2, hi3);
    }
}

// ---------------------------------------------------------------------------
// K4b: reduce 16 split-K partials. grid = 64 blocks x 256 threads.  [R3]
// ---------------------------------------------------------------------------
__global__ __launch_bounds__(256) void out2_kernel(float* __restrict__ out) {
    int g = blockIdx.x * 256 + threadIdx.x;   // 0..16383 float4 slots
    float4 a = make_float4(0.f, 0.f, 0.f, 0.f);
    #pragma unroll
    for (int ks = 0; ks < OKSPL; ks++) {
        float4 v = *(const float4*)(g_P + (size_t)ks * 65536 + 4 * (size_t)g);
        a.x += v.x; a.y += v.y; a.z += v.z; a.w += v.w;
    }
    *(float4*)(out + 4 * (size_t)g) = a;
}

// ---------------------------------------------------------------------------
// launch
// ---------------------------------------------------------------------------
extern "C" void kernel_launch(void* const* d_in, const int* in_sizes, int n_in,
                              void* d_out, int out_size) {
    const float *x = nullptr, *cosb = nullptr, *sinb = nullptr, *sink = nullptr,
                *Wqkvg = nullptr, *pw = nullptr, *Wout = nullptr, *tao = nullptr;
    for (int i = 0; i < n_in; i++) {
        const float* p = (const float*)d_in[i];
        switch (in_sizes[i]) {
            case 8 * 8192 * 128: x = p; break;
            case 65 * 64: if (!cosb) cosb = p; else sinb = p; break;
            case 8 * 128: sink = p; break;
            case 4096 * 128: Wqkvg = p; break;
            case 2048: pw = p; break;
            case 128 * 1024: Wout = p; break;
            case 2: tao = p; break;
            default: break;
        }
    }
    float* out = (float*)d_out;

    cudaFuncSetAttribute(attn_kernel, cudaFuncAttributeMaxDynamicSharedMemorySize,
                         ATTN_SMEM_FLOATS * (int)sizeof(float));
    cudaFuncSetAttribute(qkvg_kernel, cudaFuncAttributeMaxDynamicSharedMemorySize,
                         QK_SMEM);
    cudaFuncSetAttribute(out1_kernel, cudaFuncAttributeMaxDynamicSharedMemorySize,
                         O1_SMEM);

    score_kernel<<<B * NP, 256>>>(x, pw);
    qkvg_kernel<<<dim3(32, B), 256, QK_SMEM>>>(x, Wqkvg);
    attn_kernel<<<dim3(2, H, B), 512, ATTN_SMEM_FLOATS * (int)sizeof(float)>>>(
        sink, cosb, sinb, tao);
    out1_kernel<<<dim3(OKSPL, B), 256, O1_SMEM>>>(Wout);
    out2_kernel<<<64, 256>>>(out);
    (void)out_size;
}